// round 6
// baseline (speedup 1.0000x reference)
#include <cuda_runtime.h>
#include <math.h>
#include <stdint.h>

#define BATCH 4
#define SEQ 2048
#define D_MODEL 512
#define NHEAD 8
#define HEAD_DIM 64
#define M_ROWS (BATCH * SEQ)      // 8192
#define QKV_N (3 * D_MODEL)       // 1536
#define K_DIM 512

// ------------------------ device scratch -----------------------------------
__device__ float g_q[BATCH * NHEAD * SEQ * HEAD_DIM];     // [B,H,S,Hd] tf32
__device__ float g_k[BATCH * NHEAD * SEQ * HEAD_DIM];     // [B,H,S,Hd] tf32
__device__ float g_vt[BATCH * NHEAD * HEAD_DIM * SEQ];    // [B,H,Hd,S] tf32
__device__ float g_att[M_ROWS * D_MODEL];                 // [B,S,D]
__device__ float g_wqkvt[QKV_N * K_DIM];                  // Wqkv^T
__device__ float g_wot[D_MODEL * D_MODEL];                // Wo^T

// ------------------------ helpers ------------------------------------------
__device__ __forceinline__ float tf32r(float x) {
    uint32_t u;
    asm("cvt.rna.tf32.f32 %0, %1;" : "=r"(u) : "f"(x));
    return __uint_as_float(u);
}

__device__ __forceinline__ float ex2f(float x) {
    float y;
    asm("ex2.approx.f32 %0, %1;" : "=f"(y) : "f"(x));
    return y;
}

__device__ __forceinline__ void mma_tf32(float c[4], const uint32_t a[4],
                                         uint32_t b0, uint32_t b1) {
    asm volatile(
        "mma.sync.aligned.m16n8k8.row.col.f32.tf32.tf32.f32 "
        "{%0,%1,%2,%3}, {%4,%5,%6,%7}, {%8,%9}, {%0,%1,%2,%3};\n"
        : "+f"(c[0]), "+f"(c[1]), "+f"(c[2]), "+f"(c[3])
        : "r"(a[0]), "r"(a[1]), "r"(a[2]), "r"(a[3]), "r"(b0), "r"(b1));
}

__device__ __forceinline__ unsigned smem_u32(const void* p) {
    return (unsigned)__cvta_generic_to_shared(p);
}

#define CP_ASYNC16(dst_u32, src_ptr) \
    asm volatile("cp.async.cg.shared.global [%0], [%1], 16;\n" \
                 :: "r"(dst_u32), "l"(src_ptr) : "memory")
#define CP_COMMIT()  asm volatile("cp.async.commit_group;" ::: "memory")
#define CP_WAIT(n)   asm volatile("cp.async.wait_group %0;" :: "n"(n) : "memory")

// ------------------------ transpose: in[R][C] -> out[C][R] ------------------
__global__ __launch_bounds__(256)
void transpose_kernel(const float* __restrict__ in, float* __restrict__ out,
                      int R, int C)
{
    __shared__ float tile[32][33];
    int cBase = blockIdx.x * 32, rBase = blockIdx.y * 32;
    int tx = threadIdx.x, ty = threadIdx.y;
#pragma unroll
    for (int i = 0; i < 32; i += 8)
        tile[ty + i][tx] = in[(size_t)(rBase + ty + i) * C + cBase + tx];
    __syncthreads();
#pragma unroll
    for (int i = 0; i < 32; i += 8)
        out[(size_t)(cBase + ty + i) * R + rBase + tx] = tile[tx][ty + i];
}

// ------------------------ tf32 GEMM (R4 version, proven) --------------------
// MODE 0: plain store. MODE 1: QKV epilogue (RoPE q/k, V transposed store).
template <int MODE>
__global__ __launch_bounds__(256, 2)
void gemm_tf32(const float* __restrict__ A, const float* __restrict__ Bt,
               const float* __restrict__ bias, float* __restrict__ C, int N)
{
    __shared__ float As[128][36];
    __shared__ float Bs[128][36];

    const int tid = threadIdx.x;
    const int lane = tid & 31;
    const int warp = tid >> 5;
    const int wm = warp >> 2;
    const int wn = warp & 3;
    const int lr = lane >> 2;
    const int lc = lane & 3;
    const int mBase = blockIdx.y * 128;
    const int nBase = blockIdx.x * 128;

    float acc[4][4][4];
#pragma unroll
    for (int mt = 0; mt < 4; mt++)
#pragma unroll
        for (int nt = 0; nt < 4; nt++)
#pragma unroll
            for (int j = 0; j < 4; j++) acc[mt][nt][j] = 0.f;

    const int cpRow = tid >> 3;
    const int cpC4 = tid & 7;

    for (int k0 = 0; k0 < K_DIM; k0 += 32) {
        __syncthreads();
#pragma unroll
        for (int i = 0; i < 4; i++) {
            int row = cpRow + i * 32;
            float4 va = *(const float4*)&A[(size_t)(mBase + row) * K_DIM + k0 + cpC4 * 4];
            va.x = tf32r(va.x); va.y = tf32r(va.y); va.z = tf32r(va.z); va.w = tf32r(va.w);
            *(float4*)&As[row][cpC4 * 4] = va;
            float4 vb = *(const float4*)&Bt[(size_t)(nBase + row) * K_DIM + k0 + cpC4 * 4];
            vb.x = tf32r(vb.x); vb.y = tf32r(vb.y); vb.z = tf32r(vb.z); vb.w = tf32r(vb.w);
            *(float4*)&Bs[row][cpC4 * 4] = vb;
        }
        __syncthreads();

#pragma unroll
        for (int kk = 0; kk < 4; kk++) {
            const int kb = kk * 8;
            uint32_t af[4][4];
#pragma unroll
            for (int mt = 0; mt < 4; mt++) {
                int r = wm * 64 + mt * 16 + lr;
                af[mt][0] = __float_as_uint(As[r][kb + lc]);
                af[mt][1] = __float_as_uint(As[r + 8][kb + lc]);
                af[mt][2] = __float_as_uint(As[r][kb + lc + 4]);
                af[mt][3] = __float_as_uint(As[r + 8][kb + lc + 4]);
            }
#pragma unroll
            for (int nt = 0; nt < 4; nt++) {
                int cn = wn * 32 + nt * 8 + lr;
                uint32_t b0 = __float_as_uint(Bs[cn][kb + lc]);
                uint32_t b1 = __float_as_uint(Bs[cn][kb + lc + 4]);
#pragma unroll
                for (int mt = 0; mt < 4; mt++)
                    mma_tf32(acc[mt][nt], af[mt], b0, b1);
            }
        }
    }

#pragma unroll
    for (int mt = 0; mt < 4; mt++) {
#pragma unroll
        for (int nt = 0; nt < 4; nt++) {
            int grow0 = mBase + wm * 64 + mt * 16 + lr;
            int gcol = nBase + wn * 32 + nt * 8 + 2 * lc;
            float b0v = bias[gcol], b1v = bias[gcol + 1];
            if (MODE == 0) {
                *(float2*)&C[(size_t)grow0 * N + gcol] =
                    make_float2(acc[mt][nt][0] + b0v, acc[mt][nt][1] + b1v);
                *(float2*)&C[(size_t)(grow0 + 8) * N + gcol] =
                    make_float2(acc[mt][nt][2] + b0v, acc[mt][nt][3] + b1v);
            } else {
                int region = gcol >> 9;          // 0=q, 1=k, 2=v
                int h = (gcol >> 6) & 7;
                int d = gcol & 63;               // even
#pragma unroll
                for (int rr = 0; rr < 2; rr++) {
                    int grow = grow0 + rr * 8;
                    int bb = grow >> 11;
                    int ss = grow & (SEQ - 1);
                    float x1 = acc[mt][nt][2 * rr] + b0v;
                    float x2 = acc[mt][nt][2 * rr + 1] + b1v;
                    if (region == 2) {
                        size_t base = ((size_t)(bb * NHEAD + h) * HEAD_DIM + d) * SEQ + ss;
                        g_vt[base] = tf32r(x1);
                        g_vt[base + SEQ] = tf32r(x2);
                    } else {
                        float inv_freq = __powf(10000.f, -(float)d * (1.f / 64.f));
                        float sn, cs;
                        __sincosf((float)ss * inv_freq, &sn, &cs);
                        float r1 = x1 * cs - x2 * sn;
                        float r2 = x1 * sn + x2 * cs;
                        float* dst = (region == 0) ? g_q : g_k;
                        *(float2*)&dst[(size_t)((bb * NHEAD + h) * SEQ + ss) * HEAD_DIM + d] =
                            make_float2(tf32r(r1), tf32r(r2));
                    }
                }
            }
        }
    }
}

// ------------------------ attention v5 --------------------------------------
// 256 thr (8 warps), 128 q rows/CTA (16/warp). Q fragments in registers
// (32 regs). Permuted k-slots: B frags = LDS.64, score frag == PV A frag.
// K/V double-buffered via cp.async. ~130 regs -> 2 CTAs/SM, 16 warps/SM.
#define AT_S 68
#define AT_STAGE (2 * 64 * AT_S)            // K tile + VT tile (floats) = 8704
#define AT_SMEM (2 * AT_STAGE * 4)          // 69632 bytes

__global__ __launch_bounds__(256, 2)
void attention_tf32_v5()
{
    extern __shared__ float sm[];
    const int tid = threadIdx.x;
    const int lane = tid & 31;
    const int w = tid >> 5;
    const int lr = lane >> 2;
    const int lc = lane & 3;
    const int bh = blockIdx.y;
    const int bb = bh >> 3, hh = bh & 7;
    const int row0 = blockIdx.x * 128;

    const float* qg = g_q + (size_t)bh * SEQ * HEAD_DIM;
    const float* kg = g_k + (size_t)bh * SEQ * HEAD_DIM;
    const float* vtg = g_vt + (size_t)bh * HEAD_DIM * SEQ;

    // ---- stage Q (scaled into log2 domain) through smem, extract fragments
    const float QSCALE = 0.125f * 1.44269504088896340736f;  // 1/8 * log2(e)
#pragma unroll
    for (int i = 0; i < 8; i++) {
        int idx = tid + 256 * i;
        int row = idx >> 4, c4 = idx & 15;
        float4 v = *(const float4*)&qg[(size_t)(row0 + row) * HEAD_DIM + c4 * 4];
        v.x = tf32r(v.x * QSCALE); v.y = tf32r(v.y * QSCALE);
        v.z = tf32r(v.z * QSCALE); v.w = tf32r(v.w * QSCALE);
        *(float4*)&sm[row * AT_S + c4 * 4] = v;
    }
    __syncthreads();

    const int r0 = w * 16 + lr;          // warp's first row
    uint32_t qa[8][4];                   // permuted A fragments, 32 regs
#pragma unroll
    for (int kk = 0; kk < 8; kk++) {
        int col = kk * 8 + 2 * lc;
        float2 f0 = *(const float2*)&sm[(r0) * AT_S + col];
        float2 f1 = *(const float2*)&sm[(r0 + 8) * AT_S + col];
        qa[kk][0] = __float_as_uint(f0.x);
        qa[kk][1] = __float_as_uint(f1.x);
        qa[kk][2] = __float_as_uint(f0.y);
        qa[kk][3] = __float_as_uint(f1.y);
    }
    __syncthreads();

    // ---- prefetch tile 0
    {
        float* Ksb = sm;
        float* Vsb = sm + 64 * AT_S;
#pragma unroll
        for (int i = 0; i < 4; i++) {
            int idx = tid + 256 * i;
            int row = idx >> 4, c4 = idx & 15;
            CP_ASYNC16(smem_u32(&Ksb[row * AT_S + c4 * 4]),
                       &kg[(size_t)row * HEAD_DIM + c4 * 4]);
            CP_ASYNC16(smem_u32(&Vsb[row * AT_S + c4 * 4]),
                       &vtg[(size_t)row * SEQ + c4 * 4]);
        }
        CP_COMMIT();
    }

    float o[8][4];
#pragma unroll
    for (int nt = 0; nt < 8; nt++)
#pragma unroll
        for (int j = 0; j < 4; j++) o[nt][j] = 0.f;
    float m0 = -1e30f, m1 = -1e30f, l0 = 0.f, l1 = 0.f;

    for (int t = 0; t < SEQ / 64; t++) {
        if (t < SEQ / 64 - 1) {
            float* Ksb = sm + ((t + 1) & 1) * AT_STAGE;
            float* Vsb = Ksb + 64 * AT_S;
#pragma unroll
            for (int i = 0; i < 4; i++) {
                int idx = tid + 256 * i;
                int row = idx >> 4, c4 = idx & 15;
                CP_ASYNC16(smem_u32(&Ksb[row * AT_S + c4 * 4]),
                           &kg[(size_t)((t + 1) * 64 + row) * HEAD_DIM + c4 * 4]);
                CP_ASYNC16(smem_u32(&Vsb[row * AT_S + c4 * 4]),
                           &vtg[(size_t)row * SEQ + (t + 1) * 64 + c4 * 4]);
            }
            CP_COMMIT();
            CP_WAIT(1);
        } else {
            CP_WAIT(0);
        }
        __syncthreads();

        const float* Ks = sm + (t & 1) * AT_STAGE;
        const float* Vs = Ks + 64 * AT_S;

        // ---- scores: Sc[16 x 64] = Qs @ K^T (permuted k-slots, float2 B)
        float sc[8][4];
#pragma unroll
        for (int nt = 0; nt < 8; nt++)
#pragma unroll
            for (int j = 0; j < 4; j++) sc[nt][j] = 0.f;

#pragma unroll
        for (int kk = 0; kk < 8; kk++) {
            int col = kk * 8 + 2 * lc;
#pragma unroll
            for (int nt = 0; nt < 8; nt++) {
                float2 b = *(const float2*)&Ks[(nt * 8 + lr) * AT_S + col];
                mma_tf32(sc[nt], qa[kk],
                         __float_as_uint(b.x), __float_as_uint(b.y));
            }
        }

        // ---- online softmax (base-2)
        float rmax0 = -1e30f, rmax1 = -1e30f;
#pragma unroll
        for (int nt = 0; nt < 8; nt++) {
            rmax0 = fmaxf(rmax0, fmaxf(sc[nt][0], sc[nt][1]));
            rmax1 = fmaxf(rmax1, fmaxf(sc[nt][2], sc[nt][3]));
        }
        rmax0 = fmaxf(rmax0, __shfl_xor_sync(0xffffffffu, rmax0, 1));
        rmax0 = fmaxf(rmax0, __shfl_xor_sync(0xffffffffu, rmax0, 2));
        rmax1 = fmaxf(rmax1, __shfl_xor_sync(0xffffffffu, rmax1, 1));
        rmax1 = fmaxf(rmax1, __shfl_xor_sync(0xffffffffu, rmax1, 2));

        float mn0 = fmaxf(m0, rmax0), mn1 = fmaxf(m1, rmax1);
        float corr0 = ex2f(m0 - mn0), corr1 = ex2f(m1 - mn1);
        float ls0 = 0.f, ls1 = 0.f;
#pragma unroll
        for (int nt = 0; nt < 8; nt++) {
            float p0 = ex2f(sc[nt][0] - mn0);
            float p1 = ex2f(sc[nt][1] - mn0);
            float p2 = ex2f(sc[nt][2] - mn1);
            float p3 = ex2f(sc[nt][3] - mn1);
            ls0 += p0 + p1;
            ls1 += p2 + p3;
            sc[nt][0] = tf32r(p0); sc[nt][1] = tf32r(p1);
            sc[nt][2] = tf32r(p2); sc[nt][3] = tf32r(p3);
        }
        ls0 += __shfl_xor_sync(0xffffffffu, ls0, 1);
        ls0 += __shfl_xor_sync(0xffffffffu, ls0, 2);
        ls1 += __shfl_xor_sync(0xffffffffu, ls1, 1);
        ls1 += __shfl_xor_sync(0xffffffffu, ls1, 2);
        l0 = l0 * corr0 + ls0;
        l1 = l1 * corr1 + ls1;
        m0 = mn0; m1 = mn1;
#pragma unroll
        for (int nt = 0; nt < 8; nt++) {
            o[nt][0] *= corr0; o[nt][1] *= corr0;
            o[nt][2] *= corr1; o[nt][3] *= corr1;
        }

        // ---- O += P @ V (score frag IS the A frag under slot permutation)
#pragma unroll
        for (int kk = 0; kk < 8; kk++) {
            uint32_t a[4];
            a[0] = __float_as_uint(sc[kk][0]);
            a[1] = __float_as_uint(sc[kk][2]);
            a[2] = __float_as_uint(sc[kk][1]);
            a[3] = __float_as_uint(sc[kk][3]);
            int col = kk * 8 + 2 * lc;
#pragma unroll
            for (int nt = 0; nt < 8; nt++) {
                float2 b = *(const float2*)&Vs[(nt * 8 + lr) * AT_S + col];
                mma_tf32(o[nt], a,
                         __float_as_uint(b.x), __float_as_uint(b.y));
            }
        }
        __syncthreads();
    }

    // ---- epilogue: write [B,S,D]
    float il0 = 1.f / l0, il1 = 1.f / l1;
    int srow = row0 + w * 16 + lr;
#pragma unroll
    for (int nt = 0; nt < 8; nt++) {
        int d = hh * 64 + nt * 8 + 2 * lc;
        *(float2*)&g_att[(size_t)(bb * SEQ + srow) * D_MODEL + d] =
            make_float2(o[nt][0] * il0, o[nt][1] * il0);
        *(float2*)&g_att[(size_t)(bb * SEQ + srow + 8) * D_MODEL + d] =
            make_float2(o[nt][2] * il1, o[nt][3] * il1);
    }
}

// ------------------------ launch --------------------------------------------
extern "C" void kernel_launch(void* const* d_in, const int* in_sizes, int n_in,
                              void* d_out, int out_size)
{
    const float* x    = (const float*)d_in[0];
    const float* Wqkv = (const float*)d_in[1];
    const float* bqkv = (const float*)d_in[2];
    const float* Wo   = (const float*)d_in[3];
    const float* bo   = (const float*)d_in[4];
    float* out = (float*)d_out;

    float *p_att, *p_wqkvt, *p_wot;
    cudaGetSymbolAddress((void**)&p_att, g_att);
    cudaGetSymbolAddress((void**)&p_wqkvt, g_wqkvt);
    cudaGetSymbolAddress((void**)&p_wot, g_wot);

    // transpose weights -> [N][K]
    {
        dim3 blk(32, 8);
        transpose_kernel<<<dim3(QKV_N / 32, K_DIM / 32), blk>>>(Wqkv, p_wqkvt, K_DIM, QKV_N);
        transpose_kernel<<<dim3(D_MODEL / 32, K_DIM / 32), blk>>>(Wo, p_wot, K_DIM, D_MODEL);
    }
    // QKV projection + RoPE + split (+ tf32 pre-round, V transposed)
    {
        dim3 grid(QKV_N / 128, M_ROWS / 128);
        gemm_tf32<1><<<grid, 256>>>(x, p_wqkvt, bqkv, nullptr, QKV_N);
    }
    // attention
    {
        cudaFuncSetAttribute(attention_tf32_v5,
                             cudaFuncAttributeMaxDynamicSharedMemorySize, AT_SMEM);
        dim3 grid(SEQ / 128, BATCH * NHEAD);
        attention_tf32_v5<<<grid, 256, AT_SMEM>>>();
    }
    // output projection
    {
        dim3 grid(D_MODEL / 128, M_ROWS / 128);
        gemm_tf32<0><<<grid, 256>>>(p_att, p_wot, bo, out, D_MODEL);
    }
}

// round 7
// speedup vs baseline: 1.3915x; 1.3915x over previous
#include <cuda_runtime.h>
#include <math.h>
#include <stdint.h>

#define BATCH 4
#define SEQ 2048
#define D_MODEL 512
#define NHEAD 8
#define HEAD_DIM 64
#define M_ROWS (BATCH * SEQ)      // 8192
#define QKV_N (3 * D_MODEL)       // 1536
#define K_DIM 512

// ------------------------ device scratch -----------------------------------
__device__ float g_q[BATCH * NHEAD * SEQ * HEAD_DIM];     // [B,H,S,Hd] tf32
__device__ float g_k[BATCH * NHEAD * SEQ * HEAD_DIM];     // [B,H,S,Hd] tf32
__device__ float g_vt[BATCH * NHEAD * HEAD_DIM * SEQ];    // [B,H,Hd,S] tf32
__device__ float g_att[M_ROWS * D_MODEL];                 // [B,S,D]
__device__ float g_wqkvt[QKV_N * K_DIM];                  // Wqkv^T
__device__ float g_wot[D_MODEL * D_MODEL];                // Wo^T

// ------------------------ helpers ------------------------------------------
__device__ __forceinline__ float tf32r(float x) {
    uint32_t u;
    asm("cvt.rna.tf32.f32 %0, %1;" : "=r"(u) : "f"(x));
    return __uint_as_float(u);
}

__device__ __forceinline__ float ex2f(float x) {
    float y;
    asm("ex2.approx.f32 %0, %1;" : "=f"(y) : "f"(x));
    return y;
}

__device__ __forceinline__ void mma_tf32(float c[4], const uint32_t a[4],
                                         uint32_t b0, uint32_t b1) {
    asm volatile(
        "mma.sync.aligned.m16n8k8.row.col.f32.tf32.tf32.f32 "
        "{%0,%1,%2,%3}, {%4,%5,%6,%7}, {%8,%9}, {%0,%1,%2,%3};\n"
        : "+f"(c[0]), "+f"(c[1]), "+f"(c[2]), "+f"(c[3])
        : "r"(a[0]), "r"(a[1]), "r"(a[2]), "r"(a[3]), "r"(b0), "r"(b1));
}

__device__ __forceinline__ unsigned smem_u32(const void* p) {
    return (unsigned)__cvta_generic_to_shared(p);
}

#define CP_ASYNC16(dst_u32, src_ptr) \
    asm volatile("cp.async.cg.shared.global [%0], [%1], 16;\n" \
                 :: "r"(dst_u32), "l"(src_ptr) : "memory")
#define CP_COMMIT()  asm volatile("cp.async.commit_group;" ::: "memory")
#define CP_WAIT(n)   asm volatile("cp.async.wait_group %0;" :: "n"(n) : "memory")

// ------------------------ transpose: in[R][C] -> out[C][R] ------------------
__global__ __launch_bounds__(256)
void transpose_kernel(const float* __restrict__ in, float* __restrict__ out,
                      int R, int C)
{
    __shared__ float tile[32][33];
    int cBase = blockIdx.x * 32, rBase = blockIdx.y * 32;
    int tx = threadIdx.x, ty = threadIdx.y;
#pragma unroll
    for (int i = 0; i < 32; i += 8)
        tile[ty + i][tx] = in[(size_t)(rBase + ty + i) * C + cBase + tx];
    __syncthreads();
#pragma unroll
    for (int i = 0; i < 32; i += 8)
        out[(size_t)(cBase + ty + i) * R + rBase + tx] = tile[tx][ty + i];
}

// ------------------------ tf32 GEMM (R4 version, proven) --------------------
// MODE 0: plain store. MODE 1: QKV epilogue (RoPE q/k, V transposed store).
template <int MODE>
__global__ __launch_bounds__(256, 2)
void gemm_tf32(const float* __restrict__ A, const float* __restrict__ Bt,
               const float* __restrict__ bias, float* __restrict__ C, int N)
{
    __shared__ float As[128][36];
    __shared__ float Bs[128][36];

    const int tid = threadIdx.x;
    const int lane = tid & 31;
    const int warp = tid >> 5;
    const int wm = warp >> 2;
    const int wn = warp & 3;
    const int lr = lane >> 2;
    const int lc = lane & 3;
    const int mBase = blockIdx.y * 128;
    const int nBase = blockIdx.x * 128;

    float acc[4][4][4];
#pragma unroll
    for (int mt = 0; mt < 4; mt++)
#pragma unroll
        for (int nt = 0; nt < 4; nt++)
#pragma unroll
            for (int j = 0; j < 4; j++) acc[mt][nt][j] = 0.f;

    const int cpRow = tid >> 3;
    const int cpC4 = tid & 7;

    for (int k0 = 0; k0 < K_DIM; k0 += 32) {
        __syncthreads();
#pragma unroll
        for (int i = 0; i < 4; i++) {
            int row = cpRow + i * 32;
            float4 va = *(const float4*)&A[(size_t)(mBase + row) * K_DIM + k0 + cpC4 * 4];
            va.x = tf32r(va.x); va.y = tf32r(va.y); va.z = tf32r(va.z); va.w = tf32r(va.w);
            *(float4*)&As[row][cpC4 * 4] = va;
            float4 vb = *(const float4*)&Bt[(size_t)(nBase + row) * K_DIM + k0 + cpC4 * 4];
            vb.x = tf32r(vb.x); vb.y = tf32r(vb.y); vb.z = tf32r(vb.z); vb.w = tf32r(vb.w);
            *(float4*)&Bs[row][cpC4 * 4] = vb;
        }
        __syncthreads();

#pragma unroll
        for (int kk = 0; kk < 4; kk++) {
            const int kb = kk * 8;
            uint32_t af[4][4];
#pragma unroll
            for (int mt = 0; mt < 4; mt++) {
                int r = wm * 64 + mt * 16 + lr;
                af[mt][0] = __float_as_uint(As[r][kb + lc]);
                af[mt][1] = __float_as_uint(As[r + 8][kb + lc]);
                af[mt][2] = __float_as_uint(As[r][kb + lc + 4]);
                af[mt][3] = __float_as_uint(As[r + 8][kb + lc + 4]);
            }
#pragma unroll
            for (int nt = 0; nt < 4; nt++) {
                int cn = wn * 32 + nt * 8 + lr;
                uint32_t b0 = __float_as_uint(Bs[cn][kb + lc]);
                uint32_t b1 = __float_as_uint(Bs[cn][kb + lc + 4]);
#pragma unroll
                for (int mt = 0; mt < 4; mt++)
                    mma_tf32(acc[mt][nt], af[mt], b0, b1);
            }
        }
    }

#pragma unroll
    for (int mt = 0; mt < 4; mt++) {
#pragma unroll
        for (int nt = 0; nt < 4; nt++) {
            int grow0 = mBase + wm * 64 + mt * 16 + lr;
            int gcol = nBase + wn * 32 + nt * 8 + 2 * lc;
            float b0v = bias[gcol], b1v = bias[gcol + 1];
            if (MODE == 0) {
                *(float2*)&C[(size_t)grow0 * N + gcol] =
                    make_float2(acc[mt][nt][0] + b0v, acc[mt][nt][1] + b1v);
                *(float2*)&C[(size_t)(grow0 + 8) * N + gcol] =
                    make_float2(acc[mt][nt][2] + b0v, acc[mt][nt][3] + b1v);
            } else {
                int region = gcol >> 9;          // 0=q, 1=k, 2=v
                int h = (gcol >> 6) & 7;
                int d = gcol & 63;               // even
#pragma unroll
                for (int rr = 0; rr < 2; rr++) {
                    int grow = grow0 + rr * 8;
                    int bb = grow >> 11;
                    int ss = grow & (SEQ - 1);
                    float x1 = acc[mt][nt][2 * rr] + b0v;
                    float x2 = acc[mt][nt][2 * rr + 1] + b1v;
                    if (region == 2) {
                        size_t base = ((size_t)(bb * NHEAD + h) * HEAD_DIM + d) * SEQ + ss;
                        g_vt[base] = tf32r(x1);
                        g_vt[base + SEQ] = tf32r(x2);
                    } else {
                        float inv_freq = __powf(10000.f, -(float)d * (1.f / 64.f));
                        float sn, cs;
                        __sincosf((float)ss * inv_freq, &sn, &cs);
                        float r1 = x1 * cs - x2 * sn;
                        float r2 = x1 * sn + x2 * cs;
                        float* dst = (region == 0) ? g_q : g_k;
                        *(float2*)&dst[(size_t)((bb * NHEAD + h) * SEQ + ss) * HEAD_DIM + d] =
                            make_float2(tf32r(r1), tf32r(r2));
                    }
                }
            }
        }
    }
}

// ------------------------ attention v6 --------------------------------------
// R4 config (128 thr, 4 warps, 32 q rows/warp) with two fixes:
//  * stride 72 (conflict-free float2 B fragments: banks 8*lr+2*lc)
//  * softmax per 32-key sub-block -> sc[2][4][4] (32 regs), no spills
#define AT_S 72
#define AT_STAGE (2 * 64 * AT_S)            // K tile + VT tile = 9216 floats
#define AT_SMEM (2 * AT_STAGE * 4)          // 73728 bytes

__global__ __launch_bounds__(128, 2)
void attention_tf32_v6()
{
    extern __shared__ float sm[];
    const int tid = threadIdx.x;
    const int lane = tid & 31;
    const int w = tid >> 5;
    const int lr = lane >> 2;
    const int lc = lane & 3;
    const int bh = blockIdx.y;
    const int bb = bh >> 3, hh = bh & 7;
    const int row0 = blockIdx.x * 128;

    const float* qg = g_q + (size_t)bh * SEQ * HEAD_DIM;
    const float* kg = g_k + (size_t)bh * SEQ * HEAD_DIM;
    const float* vtg = g_vt + (size_t)bh * HEAD_DIM * SEQ;

    // ---- stage Q (scaled into log2 domain), extract permuted fragments
    const float QSCALE = 0.125f * 1.44269504088896340736f;  // 1/8 * log2(e)
#pragma unroll
    for (int i = 0; i < 16; i++) {
        int idx = tid + 128 * i;
        int row = idx >> 4, c4 = idx & 15;
        float4 v = *(const float4*)&qg[(size_t)(row0 + row) * HEAD_DIM + c4 * 4];
        v.x = tf32r(v.x * QSCALE); v.y = tf32r(v.y * QSCALE);
        v.z = tf32r(v.z * QSCALE); v.w = tf32r(v.w * QSCALE);
        *(float4*)&sm[row * AT_S + c4 * 4] = v;
    }
    __syncthreads();

    const int r0 = w * 32 + lr;          // warp's first row
    uint32_t qa[8][8];                   // [kk][tile0: a0..a3, tile1: a0..a3]
#pragma unroll
    for (int kk = 0; kk < 8; kk++) {
        int col = kk * 8 + 2 * lc;
        float2 f0 = *(const float2*)&sm[(r0) * AT_S + col];
        float2 f1 = *(const float2*)&sm[(r0 + 8) * AT_S + col];
        float2 f2 = *(const float2*)&sm[(r0 + 16) * AT_S + col];
        float2 f3 = *(const float2*)&sm[(r0 + 24) * AT_S + col];
        qa[kk][0] = __float_as_uint(f0.x); qa[kk][2] = __float_as_uint(f0.y);
        qa[kk][1] = __float_as_uint(f1.x); qa[kk][3] = __float_as_uint(f1.y);
        qa[kk][4] = __float_as_uint(f2.x); qa[kk][6] = __float_as_uint(f2.y);
        qa[kk][5] = __float_as_uint(f3.x); qa[kk][7] = __float_as_uint(f3.y);
    }
    __syncthreads();

    // ---- prefetch tile 0
    {
        float* Ksb = sm;
        float* Vsb = sm + 64 * AT_S;
#pragma unroll
        for (int i = 0; i < 8; i++) {
            int idx = tid + 128 * i;
            int row = idx >> 4, c4 = idx & 15;
            CP_ASYNC16(smem_u32(&Ksb[row * AT_S + c4 * 4]),
                       &kg[(size_t)row * HEAD_DIM + c4 * 4]);
            CP_ASYNC16(smem_u32(&Vsb[row * AT_S + c4 * 4]),
                       &vtg[(size_t)row * SEQ + c4 * 4]);
        }
        CP_COMMIT();
    }

    float o[2][8][4];
#pragma unroll
    for (int mt = 0; mt < 2; mt++)
#pragma unroll
        for (int nt = 0; nt < 8; nt++)
#pragma unroll
            for (int j = 0; j < 4; j++) o[mt][nt][j] = 0.f;
    float m[4] = {-1e30f, -1e30f, -1e30f, -1e30f};
    float l[4] = {0.f, 0.f, 0.f, 0.f};

    for (int t = 0; t < SEQ / 64; t++) {
        if (t < SEQ / 64 - 1) {
            float* Ksb = sm + ((t + 1) & 1) * AT_STAGE;
            float* Vsb = Ksb + 64 * AT_S;
#pragma unroll
            for (int i = 0; i < 8; i++) {
                int idx = tid + 128 * i;
                int row = idx >> 4, c4 = idx & 15;
                CP_ASYNC16(smem_u32(&Ksb[row * AT_S + c4 * 4]),
                           &kg[(size_t)((t + 1) * 64 + row) * HEAD_DIM + c4 * 4]);
                CP_ASYNC16(smem_u32(&Vsb[row * AT_S + c4 * 4]),
                           &vtg[(size_t)row * SEQ + (t + 1) * 64 + c4 * 4]);
            }
            CP_COMMIT();
            CP_WAIT(1);
        } else {
            CP_WAIT(0);
        }
        __syncthreads();

        const float* Ks = sm + (t & 1) * AT_STAGE;
        const float* Vs = Ks + 64 * AT_S;

        // two 32-key sub-blocks per tile
#pragma unroll
        for (int half = 0; half < 2; half++) {
            // ---- scores: Sc[32 x 32] = Qs @ K^T
            float sc[2][4][4];
#pragma unroll
            for (int mt = 0; mt < 2; mt++)
#pragma unroll
                for (int nt = 0; nt < 4; nt++)
#pragma unroll
                    for (int j = 0; j < 4; j++) sc[mt][nt][j] = 0.f;

#pragma unroll
            for (int kk = 0; kk < 8; kk++) {
                int col = kk * 8 + 2 * lc;
#pragma unroll
                for (int nt = 0; nt < 4; nt++) {
                    float2 b = *(const float2*)&Ks[(half * 32 + nt * 8 + lr) * AT_S + col];
                    uint32_t b0 = __float_as_uint(b.x), b1 = __float_as_uint(b.y);
                    mma_tf32(sc[0][nt], &qa[kk][0], b0, b1);
                    mma_tf32(sc[1][nt], &qa[kk][4], b0, b1);
                }
            }

            // ---- online softmax (base-2), per m-tile
#pragma unroll
            for (int mt = 0; mt < 2; mt++) {
                float rmax0 = -1e30f, rmax1 = -1e30f;
#pragma unroll
                for (int nt = 0; nt < 4; nt++) {
                    rmax0 = fmaxf(rmax0, fmaxf(sc[mt][nt][0], sc[mt][nt][1]));
                    rmax1 = fmaxf(rmax1, fmaxf(sc[mt][nt][2], sc[mt][nt][3]));
                }
                rmax0 = fmaxf(rmax0, __shfl_xor_sync(0xffffffffu, rmax0, 1));
                rmax0 = fmaxf(rmax0, __shfl_xor_sync(0xffffffffu, rmax0, 2));
                rmax1 = fmaxf(rmax1, __shfl_xor_sync(0xffffffffu, rmax1, 1));
                rmax1 = fmaxf(rmax1, __shfl_xor_sync(0xffffffffu, rmax1, 2));

                float mn0 = fmaxf(m[2 * mt], rmax0);
                float mn1 = fmaxf(m[2 * mt + 1], rmax1);
                float corr0 = ex2f(m[2 * mt] - mn0);
                float corr1 = ex2f(m[2 * mt + 1] - mn1);
                float ls0 = 0.f, ls1 = 0.f;
#pragma unroll
                for (int nt = 0; nt < 4; nt++) {
                    float p0 = ex2f(sc[mt][nt][0] - mn0);
                    float p1 = ex2f(sc[mt][nt][1] - mn0);
                    float p2 = ex2f(sc[mt][nt][2] - mn1);
                    float p3 = ex2f(sc[mt][nt][3] - mn1);
                    ls0 += p0 + p1;
                    ls1 += p2 + p3;
                    sc[mt][nt][0] = tf32r(p0); sc[mt][nt][1] = tf32r(p1);
                    sc[mt][nt][2] = tf32r(p2); sc[mt][nt][3] = tf32r(p3);
                }
                ls0 += __shfl_xor_sync(0xffffffffu, ls0, 1);
                ls0 += __shfl_xor_sync(0xffffffffu, ls0, 2);
                ls1 += __shfl_xor_sync(0xffffffffu, ls1, 1);
                ls1 += __shfl_xor_sync(0xffffffffu, ls1, 2);
                l[2 * mt] = l[2 * mt] * corr0 + ls0;
                l[2 * mt + 1] = l[2 * mt + 1] * corr1 + ls1;
                m[2 * mt] = mn0; m[2 * mt + 1] = mn1;
#pragma unroll
                for (int nt = 0; nt < 8; nt++) {
                    o[mt][nt][0] *= corr0; o[mt][nt][1] *= corr0;
                    o[mt][nt][2] *= corr1; o[mt][nt][3] *= corr1;
                }
            }

            // ---- O += P @ V (score frag IS the A frag under slot permutation)
#pragma unroll
            for (int kk = 0; kk < 4; kk++) {
                uint32_t a0[4], a1[4];
                a0[0] = __float_as_uint(sc[0][kk][0]);
                a0[1] = __float_as_uint(sc[0][kk][2]);
                a0[2] = __float_as_uint(sc[0][kk][1]);
                a0[3] = __float_as_uint(sc[0][kk][3]);
                a1[0] = __float_as_uint(sc[1][kk][0]);
                a1[1] = __float_as_uint(sc[1][kk][2]);
                a1[2] = __float_as_uint(sc[1][kk][1]);
                a1[3] = __float_as_uint(sc[1][kk][3]);
                int col = half * 32 + kk * 8 + 2 * lc;
#pragma unroll
                for (int nt = 0; nt < 8; nt++) {
                    float2 b = *(const float2*)&Vs[(nt * 8 + lr) * AT_S + col];
                    uint32_t b0 = __float_as_uint(b.x), b1 = __float_as_uint(b.y);
                    mma_tf32(o[0][nt], a0, b0, b1);
                    mma_tf32(o[1][nt], a1, b0, b1);
                }
            }
        }
        __syncthreads();
    }

    // ---- epilogue: write [B,S,D]
#pragma unroll
    for (int mt = 0; mt < 2; mt++) {
        float il0 = 1.f / l[2 * mt], il1 = 1.f / l[2 * mt + 1];
        int srow = row0 + w * 32 + mt * 16 + lr;
#pragma unroll
        for (int nt = 0; nt < 8; nt++) {
            int d = hh * 64 + nt * 8 + 2 * lc;
            *(float2*)&g_att[(size_t)(bb * SEQ + srow) * D_MODEL + d] =
                make_float2(o[mt][nt][0] * il0, o[mt][nt][1] * il0);
            *(float2*)&g_att[(size_t)(bb * SEQ + srow + 8) * D_MODEL + d] =
                make_float2(o[mt][nt][2] * il1, o[mt][nt][3] * il1);
        }
    }
}

// ------------------------ launch --------------------------------------------
extern "C" void kernel_launch(void* const* d_in, const int* in_sizes, int n_in,
                              void* d_out, int out_size)
{
    const float* x    = (const float*)d_in[0];
    const float* Wqkv = (const float*)d_in[1];
    const float* bqkv = (const float*)d_in[2];
    const float* Wo   = (const float*)d_in[3];
    const float* bo   = (const float*)d_in[4];
    float* out = (float*)d_out;

    float *p_att, *p_wqkvt, *p_wot;
    cudaGetSymbolAddress((void**)&p_att, g_att);
    cudaGetSymbolAddress((void**)&p_wqkvt, g_wqkvt);
    cudaGetSymbolAddress((void**)&p_wot, g_wot);

    // transpose weights -> [N][K]
    {
        dim3 blk(32, 8);
        transpose_kernel<<<dim3(QKV_N / 32, K_DIM / 32), blk>>>(Wqkv, p_wqkvt, K_DIM, QKV_N);
        transpose_kernel<<<dim3(D_MODEL / 32, K_DIM / 32), blk>>>(Wo, p_wot, K_DIM, D_MODEL);
    }
    // QKV projection + RoPE + split (+ tf32 pre-round, V transposed)
    {
        dim3 grid(QKV_N / 128, M_ROWS / 128);
        gemm_tf32<1><<<grid, 256>>>(x, p_wqkvt, bqkv, nullptr, QKV_N);
    }
    // attention
    {
        cudaFuncSetAttribute(attention_tf32_v6,
                             cudaFuncAttributeMaxDynamicSharedMemorySize, AT_SMEM);
        dim3 grid(SEQ / 128, BATCH * NHEAD);
        attention_tf32_v6<<<grid, 128, AT_SMEM>>>();
    }
    // output projection
    {
        dim3 grid(D_MODEL / 128, M_ROWS / 128);
        gemm_tf32<0><<<grid, 256>>>(p_att, p_wot, bo, out, D_MODEL);
    }
}